// round 16
// baseline (speedup 1.0000x reference)
#include <cuda_runtime.h>
#include <cuda_bf16.h>
#include <math.h>
#include <stdint.h>

#define B_ 16
#define L_ 1024
#define STATE_DIM 17
#define D_MODEL 512
#define D_STATE 128
#define D_CONV 4
#define N_LAYERS 6
#define HEADDIM 64
#define D_INNER 1024
#define NHEADS 16
#define CONV_DIM 1280          // D_INNER + 2*D_STATE
#define D_IN_PROJ 2320         // 2*D_INNER + 2*D_STATE + NHEADS
#define NTOK (B_*L_)

// ---------------- scratch (allocation-free: __device__ globals) -------------
__device__ float g_x[NTOK * D_MODEL];        // residual stream
__device__ float g_zx[NTOK * D_IN_PROJ];     // in_proj output
__device__ float g_xbc[NTOK * CONV_DIM];     // conv+silu output
__device__ float g_dtd[NTOK * NHEADS * 2];   // (softplus dt, decay) pairs
__device__ float g_y[NTOK * D_INNER];        // scan output
// split-bf16 activations (GEMM A operands)
__device__ __nv_bfloat16 g_hh[NTOK * D_MODEL];
__device__ __nv_bfloat16 g_hl[NTOK * D_MODEL];
__device__ __nv_bfloat16 g_yh[NTOK * D_INNER];
__device__ __nv_bfloat16 g_yl[NTOK * D_INNER];
// split-bf16 transposed weights [N][K] (hi/lo)
__device__ __nv_bfloat16 g_wih[N_LAYERS * D_IN_PROJ * D_MODEL];
__device__ __nv_bfloat16 g_wil[N_LAYERS * D_IN_PROJ * D_MODEL];
__device__ __nv_bfloat16 g_woh[N_LAYERS * D_MODEL * D_INNER];
__device__ __nv_bfloat16 g_wol[N_LAYERS * D_MODEL * D_INNER];
__device__ __nv_bfloat16 g_wfh[D_MODEL * D_MODEL];
__device__ __nv_bfloat16 g_wfl[D_MODEL * D_MODEL];

// ---------------- PTX helpers (plain sm_103-safe) ----------------------------
__device__ __forceinline__ uint32_t smem_to_u32(const void* smem_ptr) {
    uint32_t addr;
    asm("{ .reg .u64 tmp; cvta.to.shared.u64 tmp, %1; cvt.u32.u64 %0, tmp; }"
        : "=r"(addr) : "l"(smem_ptr));
    return addr;
}
#define CP_ASYNC16(dst, src) \
    asm volatile("cp.async.cg.shared.global [%0], [%1], 16;" \
                 :: "r"(dst), "l"(src) : "memory")
#define CP_ASYNC8(dst, src) \
    asm volatile("cp.async.ca.shared.global [%0], [%1], 8;" \
                 :: "r"(dst), "l"(src) : "memory")
#define CP_COMMIT() asm volatile("cp.async.commit_group;" ::: "memory")
#define CP_WAIT1() asm volatile("cp.async.wait_group 1;" ::: "memory")
#define CP_WAIT4() asm volatile("cp.async.wait_group 4;" ::: "memory")
#define CP_WAIT0() asm volatile("cp.async.wait_group 0;" ::: "memory")
#define LDMX4(r, addr) \
    asm volatile("ldmatrix.sync.aligned.m8n8.x4.shared.b16 {%0,%1,%2,%3}, [%4];" \
                 : "=r"((r)[0]), "=r"((r)[1]), "=r"((r)[2]), "=r"((r)[3]) \
                 : "r"(addr))
#define MMA_BF16(c, a, b) \
    asm volatile("mma.sync.aligned.m16n8k16.row.col.f32.bf16.bf16.f32 " \
                 "{%0,%1,%2,%3}, {%4,%5,%6,%7}, {%8,%9}, {%0,%1,%2,%3};" \
                 : "+f"((c)[0]), "+f"((c)[1]), "+f"((c)[2]), "+f"((c)[3]) \
                 : "r"((a)[0]), "r"((a)[1]), "r"((a)[2]), "r"((a)[3]), \
                   "r"((b)[0]), "r"((b)[1]))

// packed f32x2 math (Blackwell base ISA)
__device__ __forceinline__ unsigned long long pk2(float x, float y) {
    unsigned long long r;
    asm("mov.b64 %0, {%1, %2};" : "=l"(r) : "f"(x), "f"(y));
    return r;
}
__device__ __forceinline__ void upk2(unsigned long long v, float& x, float& y) {
    asm("mov.b64 {%0, %1}, %2;" : "=f"(x), "=f"(y) : "l"(v));
}
#define FMA2(d, a, b, c) \
    asm("fma.rn.f32x2 %0, %1, %2, %3;" : "=l"(d) : "l"(a), "l"(b), "l"(c))
#define MUL2(d, a, b) \
    asm("mul.rn.f32x2 %0, %1, %2;" : "=l"(d) : "l"(a), "l"(b))

__device__ __forceinline__ float warp_sum(float v) {
#pragma unroll
    for (int o = 16; o > 0; o >>= 1)
        v += __shfl_xor_sync(0xffffffffu, v, o);
    return v;
}

// ---------------- input projection + RoPE ----------------------------------
__global__ void input_rope_kernel(const float* __restrict__ states,
                                  const float* __restrict__ W,
                                  const float* __restrict__ bias,
                                  float* __restrict__ out) {
    int tok = blockIdx.x;
    int l = tok % L_;
    __shared__ float s[STATE_DIM];
    int t = threadIdx.x;  // 256 threads = 256 rope pairs
    if (t < STATE_DIM) s[t] = states[tok * STATE_DIM + t];
    __syncthreads();
    float x1 = bias[2 * t], x2 = bias[2 * t + 1];
#pragma unroll
    for (int k = 0; k < STATE_DIM; k++) {
        float sv = s[k];
        x1 += sv * W[k * D_MODEL + 2 * t];
        x2 += sv * W[k * D_MODEL + 2 * t + 1];
    }
    float inv = expf(-((2.0f * t) / (float)D_MODEL) * logf(10000.0f));
    float fr = (float)l * inv;
    float c = cosf(fr), sn = sinf(fr);
    out[tok * D_MODEL + 2 * t]     = x1 * c - x2 * sn;
    out[tok * D_MODEL + 2 * t + 1] = x1 * sn + x2 * c;
}

// ---------------- layernorm -> split bf16 (warp per token, no barriers) -----
__global__ __launch_bounds__(256) void layernorm_split_kernel(
    const float* __restrict__ x, const float* __restrict__ g,
    const float* __restrict__ b,
    __nv_bfloat16* __restrict__ oh, __nv_bfloat16* __restrict__ ol) {
    int w = threadIdx.x >> 5, lane = threadIdx.x & 31;
    int tok = blockIdx.x * 8 + w;
    const float4* xr = (const float4*)(x + (size_t)tok * D_MODEL);
    float4 a[4];
    float sm = 0.0f, sq = 0.0f;
#pragma unroll
    for (int i = 0; i < 4; i++) {
        a[i] = xr[lane + 32 * i];
        sm += a[i].x + a[i].y + a[i].z + a[i].w;
        sq += a[i].x * a[i].x + a[i].y * a[i].y +
              a[i].z * a[i].z + a[i].w * a[i].w;
    }
    sm = warp_sum(sm);
    sq = warp_sum(sq);
    float mu = sm * (1.0f / D_MODEL);
    float inv = rsqrtf(sq * (1.0f / D_MODEL) - mu * mu + 1e-5f);
    const float4* g4 = (const float4*)g;
    const float4* b4 = (const float4*)b;
    uint2* oh2 = (uint2*)(oh + (size_t)tok * D_MODEL);
    uint2* ol2 = (uint2*)(ol + (size_t)tok * D_MODEL);
#pragma unroll
    for (int i = 0; i < 4; i++) {
        int idx = lane + 32 * i;
        float4 gv = g4[idx], bv = b4[idx];
        float o0 = (a[i].x - mu) * inv * gv.x + bv.x;
        float o1 = (a[i].y - mu) * inv * gv.y + bv.y;
        float o2 = (a[i].z - mu) * inv * gv.z + bv.z;
        float o3 = (a[i].w - mu) * inv * gv.w + bv.w;
        __nv_bfloat16 h0 = __float2bfloat16(o0), h1 = __float2bfloat16(o1);
        __nv_bfloat16 h2 = __float2bfloat16(o2), h3 = __float2bfloat16(o3);
        uint2 hp, lp;
        hp.x = ((uint32_t)__bfloat16_as_ushort(h1) << 16) | __bfloat16_as_ushort(h0);
        hp.y = ((uint32_t)__bfloat16_as_ushort(h3) << 16) | __bfloat16_as_ushort(h2);
        __nv_bfloat16 l0 = __float2bfloat16(o0 - __bfloat162float(h0));
        __nv_bfloat16 l1 = __float2bfloat16(o1 - __bfloat162float(h1));
        __nv_bfloat16 l2 = __float2bfloat16(o2 - __bfloat162float(h2));
        __nv_bfloat16 l3 = __float2bfloat16(o3 - __bfloat162float(h3));
        lp.x = ((uint32_t)__bfloat16_as_ushort(l1) << 16) | __bfloat16_as_ushort(l0);
        lp.y = ((uint32_t)__bfloat16_as_ushort(l3) << 16) | __bfloat16_as_ushort(l2);
        oh2[idx] = hp;
        ol2[idx] = lp;
    }
}

// ---------------- weight transpose + bf16 hi/lo split -----------------------
__global__ void transpose_split_kernel(const float* __restrict__ W,
                                       __nv_bfloat16* __restrict__ Th,
                                       __nv_bfloat16* __restrict__ Tl,
                                       int K, int N) {
    __shared__ float tile[32][33];
    int k0 = blockIdx.x * 32, n0 = blockIdx.y * 32;
    int tx = threadIdx.x, ty = threadIdx.y;  // 32 x 8
#pragma unroll
    for (int r = ty; r < 32; r += 8) {
        int n = n0 + tx;
        tile[r][tx] = (n < N) ? W[(size_t)(k0 + r) * N + n] : 0.0f;
    }
    __syncthreads();
#pragma unroll
    for (int r = ty; r < 32; r += 8) {
        int n = n0 + r, k = k0 + tx;
        if (n < N) {
            float v = tile[tx][r];
            __nv_bfloat16 h = __float2bfloat16(v);
            __nv_bfloat16 l = __float2bfloat16(v - __bfloat162float(h));
            Th[(size_t)n * K + k] = h;
            Tl[(size_t)n * K + k] = l;
        }
    }
}

// ---------------- split-bf16 HMMA GEMM (R12, unchanged) ----------------------
#define GKC 32
#define ROWB 80
#define OFF_AH 0
#define OFF_AL 10240
#define OFF_BH 20480
#define OFF_BL 30720
#define STG_BYTES 40960
#define GEMM_SMEM (2 * STG_BYTES)

__device__ __forceinline__ void gemm_fill(
    uint32_t sa, int tid,
    const __nv_bfloat16* __restrict__ Ah, const __nv_bfloat16* __restrict__ Al,
    const __nv_bfloat16* __restrict__ Bh, const __nv_bfloat16* __restrict__ Bl,
    int m0, int n0, int N, int K, int k0) {
#pragma unroll
    for (int c = tid; c < 512; c += 256) {
        int row = c >> 2, q = c & 3;
        uint32_t d = sa + row * ROWB + q * 16;
        size_t aoff = (size_t)(m0 + row) * K + k0 + q * 8;
        CP_ASYNC16(d + OFF_AH, Ah + aoff);
        CP_ASYNC16(d + OFF_AL, Al + aoff);
        int nr = n0 + row; if (nr >= N) nr = N - 1;
        size_t boff = (size_t)nr * K + k0 + q * 8;
        CP_ASYNC16(d + OFF_BH, Bh + boff);
        CP_ASYNC16(d + OFF_BL, Bl + boff);
    }
    CP_COMMIT();
}

__global__ __launch_bounds__(256) void hmma_gemm_kernel(
    const __nv_bfloat16* __restrict__ Ah, const __nv_bfloat16* __restrict__ Al,
    const __nv_bfloat16* __restrict__ Bh, const __nv_bfloat16* __restrict__ Bl,
    const float* __restrict__ bias, const float* __restrict__ res,
    float* __restrict__ C, int M, int N, int K) {
    extern __shared__ char smem[];
    uint32_t sb = smem_to_u32(smem);
    int tid = threadIdx.x;
    int warp = tid >> 5, lane = tid & 31;
    int grp = lane >> 2, qid = lane & 3;
    int wm = (warp >> 2) * 64;
    int wn = (warp & 3) * 32;
    int brow = blockIdx.y, bcol = blockIdx.x;
    int m0 = brow * 128, n0 = bcol * 128;

    float acc[4][4][4];
#pragma unroll
    for (int i = 0; i < 4; i++)
#pragma unroll
        for (int j = 0; j < 4; j++)
#pragma unroll
            for (int r = 0; r < 4; r++) acc[i][j][r] = 0.0f;

    int lr = lane & 7;
    int arow = ((lane >> 3) & 1) * 8;
    int acol = (lane >> 4) * 16;
    int brw  = (lane >> 4) * 8;
    int bcl  = ((lane >> 3) & 1) * 16;

    int nch = K / GKC;
    gemm_fill(sb, tid, Ah, Al, Bh, Bl, m0, n0, N, K, 0);

    for (int ch = 0; ch < nch; ch++) {
        if (ch + 1 < nch) {
            gemm_fill(sb + ((ch + 1) & 1) * STG_BYTES, tid,
                      Ah, Al, Bh, Bl, m0, n0, N, K, (ch + 1) * GKC);
            CP_WAIT1();
        } else {
            CP_WAIT0();
        }
        __syncthreads();
        uint32_t sa = sb + (ch & 1) * STG_BYTES;
#pragma unroll
        for (int ks = 0; ks < 2; ks++) {
            int kb = ks * 32;
            uint32_t ah[4][4], al[4][4];
#pragma unroll
            for (int mi = 0; mi < 4; mi++) {
                uint32_t r = sa + OFF_AH +
                    (uint32_t)((wm + mi * 16 + lr + arow) * ROWB + kb + acol);
                LDMX4(ah[mi], r);
                LDMX4(al[mi], r + (OFF_AL - OFF_AH));
            }
            uint32_t bh[4][2], bl[4][2];
#pragma unroll
            for (int nb = 0; nb < 2; nb++) {
                uint32_t r = sa + OFF_BH +
                    (uint32_t)((wn + nb * 16 + lr + brw) * ROWB + kb + bcl);
                uint32_t tb[4];
                LDMX4(tb, r);
                bh[2 * nb][0] = tb[0]; bh[2 * nb][1] = tb[1];
                bh[2 * nb + 1][0] = tb[2]; bh[2 * nb + 1][1] = tb[3];
                LDMX4(tb, r + (OFF_BL - OFF_BH));
                bl[2 * nb][0] = tb[0]; bl[2 * nb][1] = tb[1];
                bl[2 * nb + 1][0] = tb[2]; bl[2 * nb + 1][1] = tb[3];
            }
#pragma unroll
            for (int mi = 0; mi < 4; mi++)
#pragma unroll
                for (int ni = 0; ni < 4; ni++) {
                    MMA_BF16(acc[mi][ni], ah[mi], bh[ni]);
                    MMA_BF16(acc[mi][ni], ah[mi], bl[ni]);
                    MMA_BF16(acc[mi][ni], al[mi], bh[ni]);
                }
        }
        __syncthreads();
    }

#pragma unroll
    for (int mi = 0; mi < 4; mi++) {
#pragma unroll
        for (int half = 0; half < 2; half++) {
            int grow = m0 + wm + mi * 16 + grp + half * 8;
#pragma unroll
            for (int ni = 0; ni < 4; ni++) {
                int gcol = n0 + wn + ni * 8 + qid * 2;
                if (gcol < N) {
                    float v0 = acc[mi][ni][half * 2 + 0];
                    float v1 = acc[mi][ni][half * 2 + 1];
                    if (bias) { v0 += bias[gcol]; v1 += bias[gcol + 1]; }
                    if (res) {
                        const float* rp = res + (size_t)grow * N + gcol;
                        v0 += rp[0]; v1 += rp[1];
                    }
                    *(float2*)(C + (size_t)grow * N + gcol) = make_float2(v0, v1);
                }
            }
        }
    }
}

// ---------------- causal conv1d + SiLU + fused dt/decay ---------------------
#define CTOK 16
__global__ __launch_bounds__(256) void conv_silu_dt_kernel(
    const float* __restrict__ zx, const float* __restrict__ cw,
    const float* __restrict__ cb, const float* __restrict__ dt_bias,
    const float* __restrict__ A_log, float* __restrict__ xbc,
    float* __restrict__ dtd) {
    int c = blockIdx.x * 256 + threadIdx.x;            // 0..1279 (grid.x = 5)
    int by = blockIdx.y;                               // 0..1023
    int b = by >> 6;
    int t0 = (by & 63) * CTOK;
    float4 w = *(const float4*)(cw + c * 4);
    float bias = cb[c];
    const float* p = zx + (size_t)(b * L_ + t0) * D_IN_PROJ + D_INNER + c;
    float* o = xbc + (size_t)(b * L_ + t0) * CONV_DIM + c;
    float x1, x2, x3;   // x_{l-1}, x_{l-2}, x_{l-3}
    if (t0 == 0) {
        x1 = x2 = x3 = 0.0f;
    } else {
        x1 = p[-(int)D_IN_PROJ];
        x2 = p[-2 * (int)D_IN_PROJ];
        x3 = p[-3 * (int)D_IN_PROJ];
    }
#pragma unroll
    for (int i = 0; i < CTOK; i++) {
        float x0 = p[0];
        float acc = bias + w.x * x3 + w.y * x2 + w.z * x1 + w.w * x0;
        o[0] = acc / (1.0f + expf(-acc));
        x3 = x2; x2 = x1; x1 = x0;
        p += D_IN_PROJ;
        o += CONV_DIM;
    }
    // fused dt/decay: block x=0 handles its 16 tokens x 16 heads
    if (blockIdx.x == 0) {
        int h = threadIdx.x & 15;
        int tok = b * L_ + t0 + (threadIdx.x >> 4);
        float v = zx[(size_t)tok * D_IN_PROJ + D_INNER + CONV_DIM + h]
                  + dt_bias[h];
        float sp = (v > 20.0f) ? v : log1pf(expf(v));
        float A = -expf(A_log[h]);
        size_t i = (size_t)tok * NHEADS + h;
        dtd[2 * i]     = sp;
        dtd[2 * i + 1] = expf(sp * A);
    }
}

// ---------------- selective scan (cp.async 6-stage pipelined) ----------------
// grid = (NHEADS, B_), block 256. Thread t: p = t>>2, q = t&3; owns contiguous
// n in [q*32, q*32+32) as 16 packed f32x2. One cp.async group per timestep;
// prefetch depth 5, wait_group 4 -> ~5 iters of latency cover.
#define SST 6
__global__ __launch_bounds__(256) void scan_kernel(
    const float* __restrict__ xbc, const float* __restrict__ dtd,
    const float* __restrict__ Dp, float* __restrict__ y) {
    int h = blockIdx.x, b = blockIdx.y;
    int t = threadIdx.x;
    int p = t >> 2;
    int q = t & 3;
    __shared__ float4 sB4[SST][36], sC4[SST][36];   // 4 q-rows x 9 float4 (pad)
    __shared__ float sX[SST][HEADDIM];
    __shared__ float2 sDt[SST];
    float Dh = Dp[h];
    unsigned long long s2[16];
#pragma unroll
    for (int j = 0; j < 16; j++) s2[j] = 0ull;

    uint32_t aB = smem_to_u32(sB4);
    uint32_t aC = smem_to_u32(sC4);
    uint32_t aX = smem_to_u32(sX);
    uint32_t aD = smem_to_u32(sDt);

    const float* xb0 = xbc + (size_t)(b * L_) * CONV_DIM;
    const float* dt0 = dtd + (size_t)(b * L_) * (NHEADS * 2) + h * 2;

    // role-based chunk issue for timestep l
#define SCAN_ISSUE(l) do {                                                    \
        int _st = (l) % SST;                                                  \
        const float* _base = xb0 + (size_t)(l) * CONV_DIM;                    \
        if (t < 32) {                                                         \
            CP_ASYNC16(aB + _st * 576 + (t >> 3) * 144 + (t & 7) * 16,        \
                       _base + D_INNER + t * 4);                              \
        } else if (t < 64) {                                                  \
            int _i = t - 32;                                                  \
            CP_ASYNC16(aC + _st * 576 + (_i >> 3) * 144 + (_i & 7) * 16,      \
                       _base + D_INNER + D_STATE + _i * 4);                   \
        } else if (t < 80) {                                                  \
            int _i = t - 64;                                                  \
            CP_ASYNC16(aX + _st * 256 + _i * 16, _base + h * HEADDIM + _i * 4); \
        } else if (t == 80) {                                                 \
            CP_ASYNC8(aD + _st * 8, dt0 + (size_t)(l) * (NHEADS * 2));        \
        }                                                                     \
    } while (0)

    SCAN_ISSUE(0); CP_COMMIT();
    SCAN_ISSUE(1); CP_COMMIT();
    SCAN_ISSUE(2); CP_COMMIT();
    SCAN_ISSUE(3); CP_COMMIT();
    SCAN_ISSUE(4); CP_COMMIT();

    int q9 = q * 9;
    for (int l = 0; l < L_; l++) {
        CP_WAIT4();
        __syncthreads();
        int cur = l % SST;
        float2 dd = sDt[cur];
        float dtv = dd.x, dec = dd.y;
        float xp = sX[cur][p];
        float dtx = dtv * xp;
        unsigned long long dec2 = pk2(dec, dec);
        unsigned long long dtx2 = pk2(dtx, dtx);
        unsigned long long acc2 = 0ull;
#pragma unroll
        for (int jj = 0; jj < 8; jj++) {
            ulonglong2 b2 = *(const ulonglong2*)&sB4[cur][q9 + jj];
            ulonglong2 c2 = *(const ulonglong2*)&sC4[cur][q9 + jj];
            unsigned long long tmp;
            MUL2(tmp, dtx2, b2.x);
            FMA2(s2[2 * jj], s2[2 * jj], dec2, tmp);
            FMA2(acc2, s2[2 * jj], c2.x, acc2);
            MUL2(tmp, dtx2, b2.y);
            FMA2(s2[2 * jj + 1], s2[2 * jj + 1], dec2, tmp);
            FMA2(acc2, s2[2 * jj + 1], c2.y, acc2);
        }
        float a0, a1;
        upk2(acc2, a0, a1);
        float acc = a0 + a1;
        acc += __shfl_xor_sync(0xffffffffu, acc, 1);
        acc += __shfl_xor_sync(0xffffffffu, acc, 2);
        if (q == 0)
            y[(size_t)(b * L_ + l) * D_INNER + h * HEADDIM + p] = acc + Dh * xp;
        if (l + 5 < L_) SCAN_ISSUE(l + 5);
        CP_COMMIT();   // always commit: keeps group-count invariant
    }
#undef SCAN_ISSUE
}

// ---------------- gate (y * silu(z)) + RMSNorm -> split bf16 (warp/token) ---
__global__ __launch_bounds__(256) void gate_rms_split_kernel(
    const float* __restrict__ zx, const float* __restrict__ rms_w,
    const float* __restrict__ y,
    __nv_bfloat16* __restrict__ oh, __nv_bfloat16* __restrict__ ol) {
    int w = threadIdx.x >> 5, lane = threadIdx.x & 31;
    int tok = blockIdx.x * 8 + w;
    const float4* zr = (const float4*)(zx + (size_t)tok * D_IN_PROJ);
    const float4* yr = (const float4*)(y + (size_t)tok * D_INNER);
    float v[32];
    float ss = 0.0f;
#pragma unroll
    for (int i = 0; i < 8; i++) {
        int idx = lane + 32 * i;
        float4 z4 = zr[idx];
        float4 y4 = yr[idx];
        float g0 = z4.x / (1.0f + expf(-z4.x));
        float g1 = z4.y / (1.0f + expf(-z4.y));
        float g2 = z4.z / (1.0f + expf(-z4.z));
        float g3 = z4.w / (1.0f + expf(-z4.w));
        v[4 * i + 0] = y4.x * g0;
        v[4 * i + 1] = y4.y * g1;
        v[4 * i + 2] = y4.z * g2;
        v[4 * i + 3] = y4.w * g3;
        ss += v[4 * i] * v[4 * i] + v[4 * i + 1] * v[4 * i + 1] +
              v[4 * i + 2] * v[4 * i + 2] + v[4 * i + 3] * v[4 * i + 3];
    }
    ss = warp_sum(ss);
    float inv = rsqrtf(ss * (1.0f / D_INNER) + 1e-5f);
    const float4* r4 = (const float4*)rms_w;
    uint2* oh2 = (uint2*)(oh + (size_t)tok * D_INNER);
    uint2* ol2 = (uint2*)(ol + (size_t)tok * D_INNER);
#pragma unroll
    for (int i = 0; i < 8; i++) {
        int idx = lane + 32 * i;
        float4 rw = r4[idx];
        float o0 = v[4 * i + 0] * inv * rw.x;
        float o1 = v[4 * i + 1] * inv * rw.y;
        float o2 = v[4 * i + 2] * inv * rw.z;
        float o3 = v[4 * i + 3] * inv * rw.w;
        __nv_bfloat16 h0 = __float2bfloat16(o0), h1 = __float2bfloat16(o1);
        __nv_bfloat16 h2 = __float2bfloat16(o2), h3 = __float2bfloat16(o3);
        uint2 hp, lp;
        hp.x = ((uint32_t)__bfloat16_as_ushort(h1) << 16) | __bfloat16_as_ushort(h0);
        hp.y = ((uint32_t)__bfloat16_as_ushort(h3) << 16) | __bfloat16_as_ushort(h2);
        __nv_bfloat16 l0 = __float2bfloat16(o0 - __bfloat162float(h0));
        __nv_bfloat16 l1 = __float2bfloat16(o1 - __bfloat162float(h1));
        __nv_bfloat16 l2 = __float2bfloat16(o2 - __bfloat162float(h2));
        __nv_bfloat16 l3 = __float2bfloat16(o3 - __bfloat162float(h3));
        lp.x = ((uint32_t)__bfloat16_as_ushort(l1) << 16) | __bfloat16_as_ushort(l0);
        lp.y = ((uint32_t)__bfloat16_as_ushort(l3) << 16) | __bfloat16_as_ushort(l2);
        oh2[idx] = hp;
        ol2[idx] = lp;
    }
}

// ---------------- launch -----------------------------------------------------
extern "C" void kernel_launch(void* const* d_in, const int* in_sizes, int n_in,
                              void* d_out, int out_size) {
    const float* states        = (const float*)d_in[0];
    const float* input_proj_w  = (const float*)d_in[1];
    const float* input_proj_b  = (const float*)d_in[2];
    const float* ln_g          = (const float*)d_in[3];
    const float* ln_b          = (const float*)d_in[4];
    const float* in_proj_w     = (const float*)d_in[5];
    const float* conv_w        = (const float*)d_in[6];
    const float* conv_b        = (const float*)d_in[7];
    const float* dt_bias       = (const float*)d_in[8];
    const float* A_log         = (const float*)d_in[9];
    const float* D_param       = (const float*)d_in[10];
    const float* rms_w         = (const float*)d_in[11];
    const float* out_proj_w    = (const float*)d_in[12];
    const float* post_ln_g     = (const float*)d_in[13];
    const float* post_ln_b     = (const float*)d_in[14];
    const float* output_proj_w = (const float*)d_in[15];
    const float* output_proj_b = (const float*)d_in[16];

    float *px, *pzx, *pxbc, *pdtd, *py;
    cudaGetSymbolAddress((void**)&px, g_x);
    cudaGetSymbolAddress((void**)&pzx, g_zx);
    cudaGetSymbolAddress((void**)&pxbc, g_xbc);
    cudaGetSymbolAddress((void**)&pdtd, g_dtd);
    cudaGetSymbolAddress((void**)&py, g_y);
    __nv_bfloat16 *phh, *phl, *pyh, *pyl;
    cudaGetSymbolAddress((void**)&phh, g_hh);
    cudaGetSymbolAddress((void**)&phl, g_hl);
    cudaGetSymbolAddress((void**)&pyh, g_yh);
    cudaGetSymbolAddress((void**)&pyl, g_yl);
    __nv_bfloat16 *pwih, *pwil, *pwoh, *pwol, *pwfh, *pwfl;
    cudaGetSymbolAddress((void**)&pwih, g_wih);
    cudaGetSymbolAddress((void**)&pwil, g_wil);
    cudaGetSymbolAddress((void**)&pwoh, g_woh);
    cudaGetSymbolAddress((void**)&pwol, g_wol);
    cudaGetSymbolAddress((void**)&pwfh, g_wfh);
    cudaGetSymbolAddress((void**)&pwfl, g_wfl);

    cudaFuncSetAttribute(hmma_gemm_kernel,
                         cudaFuncAttributeMaxDynamicSharedMemorySize, GEMM_SMEM);

    // ---- pre-split weights ----
    dim3 tb(32, 8);
    for (int l = 0; l < N_LAYERS; l++) {
        transpose_split_kernel<<<dim3(D_MODEL / 32, (D_IN_PROJ + 31) / 32), tb>>>(
            in_proj_w + (size_t)l * D_MODEL * D_IN_PROJ,
            pwih + (size_t)l * D_IN_PROJ * D_MODEL,
            pwil + (size_t)l * D_IN_PROJ * D_MODEL, D_MODEL, D_IN_PROJ);
        transpose_split_kernel<<<dim3(D_INNER / 32, D_MODEL / 32), tb>>>(
            out_proj_w + (size_t)l * D_INNER * D_MODEL,
            pwoh + (size_t)l * D_MODEL * D_INNER,
            pwol + (size_t)l * D_MODEL * D_INNER, D_INNER, D_MODEL);
    }
    transpose_split_kernel<<<dim3(D_MODEL / 32, D_MODEL / 32), tb>>>(
        output_proj_w, pwfh, pwfl, D_MODEL, D_MODEL);

    input_rope_kernel<<<NTOK, 256>>>(states, input_proj_w, input_proj_b, px);

    for (int l = 0; l < N_LAYERS; l++) {
        layernorm_split_kernel<<<NTOK / 8, 256>>>(px, ln_g + l * D_MODEL,
                                                  ln_b + l * D_MODEL, phh, phl);

        dim3 g1((D_IN_PROJ + 127) / 128, NTOK / 128);
        hmma_gemm_kernel<<<g1, 256, GEMM_SMEM>>>(
            phh, phl,
            pwih + (size_t)l * D_IN_PROJ * D_MODEL,
            pwil + (size_t)l * D_IN_PROJ * D_MODEL,
            nullptr, nullptr, pzx, NTOK, D_IN_PROJ, D_MODEL);

        conv_silu_dt_kernel<<<dim3(5, B_ * (L_ / CTOK)), 256>>>(
            pzx, conv_w + (size_t)l * CONV_DIM * D_CONV,
            conv_b + (size_t)l * CONV_DIM, dt_bias + l * NHEADS,
            A_log + l * NHEADS, pxbc, pdtd);

        scan_kernel<<<dim3(NHEADS, B_), 256>>>(pxbc, pdtd,
                                               D_param + l * NHEADS, py);

        gate_rms_split_kernel<<<NTOK / 8, 256>>>(pzx, rms_w + (size_t)l * D_INNER,
                                                 py, pyh, pyl);

        dim3 g2(D_MODEL / 128, NTOK / 128);
        hmma_gemm_kernel<<<g2, 256, GEMM_SMEM>>>(
            pyh, pyl,
            pwoh + (size_t)l * D_MODEL * D_INNER,
            pwol + (size_t)l * D_MODEL * D_INNER,
            nullptr, px, px, NTOK, D_MODEL, D_INNER);
    }

    layernorm_split_kernel<<<NTOK / 8, 256>>>(px, post_ln_g, post_ln_b, phh, phl);
    dim3 g3(D_MODEL / 128, NTOK / 128);
    hmma_gemm_kernel<<<g3, 256, GEMM_SMEM>>>(
        phh, phl, pwfh, pwfl, output_proj_b, nullptr,
        (float*)d_out, NTOK, D_MODEL, D_MODEL);
}

// round 17
// speedup vs baseline: 1.0878x; 1.0878x over previous
#include <cuda_runtime.h>
#include <cuda_bf16.h>
#include <math.h>
#include <stdint.h>

#define B_ 16
#define L_ 1024
#define STATE_DIM 17
#define D_MODEL 512
#define D_STATE 128
#define D_CONV 4
#define N_LAYERS 6
#define HEADDIM 64
#define D_INNER 1024
#define NHEADS 16
#define CONV_DIM 1280          // D_INNER + 2*D_STATE
#define D_IN_PROJ 2320         // 2*D_INNER + 2*D_STATE + NHEADS
#define NTOK (B_*L_)

// ---------------- scratch (allocation-free: __device__ globals) -------------
__device__ float g_x[NTOK * D_MODEL];        // residual stream
__device__ float g_zx[NTOK * D_IN_PROJ];     // in_proj output
__device__ float g_xbc[NTOK * CONV_DIM];     // conv+silu output
__device__ float g_dtd[NTOK * NHEADS * 2];   // (softplus dt, decay) pairs
__device__ float g_y[NTOK * D_INNER];        // scan output
// split-bf16 activations (GEMM A operands)
__device__ __nv_bfloat16 g_hh[NTOK * D_MODEL];
__device__ __nv_bfloat16 g_hl[NTOK * D_MODEL];
__device__ __nv_bfloat16 g_yh[NTOK * D_INNER];
__device__ __nv_bfloat16 g_yl[NTOK * D_INNER];
// split-bf16 transposed weights [N][K] (hi/lo)
__device__ __nv_bfloat16 g_wih[N_LAYERS * D_IN_PROJ * D_MODEL];
__device__ __nv_bfloat16 g_wil[N_LAYERS * D_IN_PROJ * D_MODEL];
__device__ __nv_bfloat16 g_woh[N_LAYERS * D_MODEL * D_INNER];
__device__ __nv_bfloat16 g_wol[N_LAYERS * D_MODEL * D_INNER];
__device__ __nv_bfloat16 g_wfh[D_MODEL * D_MODEL];
__device__ __nv_bfloat16 g_wfl[D_MODEL * D_MODEL];

// ---------------- PTX helpers (plain sm_103-safe) ----------------------------
__device__ __forceinline__ uint32_t smem_to_u32(const void* smem_ptr) {
    uint32_t addr;
    asm("{ .reg .u64 tmp; cvta.to.shared.u64 tmp, %1; cvt.u32.u64 %0, tmp; }"
        : "=r"(addr) : "l"(smem_ptr));
    return addr;
}
#define CP_ASYNC16(dst, src) \
    asm volatile("cp.async.cg.shared.global [%0], [%1], 16;" \
                 :: "r"(dst), "l"(src) : "memory")
#define CP_ASYNC8(dst, src) \
    asm volatile("cp.async.ca.shared.global [%0], [%1], 8;" \
                 :: "r"(dst), "l"(src) : "memory")
#define CP_COMMIT() asm volatile("cp.async.commit_group;" ::: "memory")
#define CP_WAIT1() asm volatile("cp.async.wait_group 1;" ::: "memory")
#define CP_WAIT0() asm volatile("cp.async.wait_group 0;" ::: "memory")
#define LDMX4(r, addr) \
    asm volatile("ldmatrix.sync.aligned.m8n8.x4.shared.b16 {%0,%1,%2,%3}, [%4];" \
                 : "=r"((r)[0]), "=r"((r)[1]), "=r"((r)[2]), "=r"((r)[3]) \
                 : "r"(addr))
#define MMA_BF16(c, a, b) \
    asm volatile("mma.sync.aligned.m16n8k16.row.col.f32.bf16.bf16.f32 " \
                 "{%0,%1,%2,%3}, {%4,%5,%6,%7}, {%8,%9}, {%0,%1,%2,%3};" \
                 : "+f"((c)[0]), "+f"((c)[1]), "+f"((c)[2]), "+f"((c)[3]) \
                 : "r"((a)[0]), "r"((a)[1]), "r"((a)[2]), "r"((a)[3]), \
                   "r"((b)[0]), "r"((b)[1]))

// packed f32x2 math (Blackwell base ISA)
__device__ __forceinline__ unsigned long long pk2(float x, float y) {
    unsigned long long r;
    asm("mov.b64 %0, {%1, %2};" : "=l"(r) : "f"(x), "f"(y));
    return r;
}
__device__ __forceinline__ void upk2(unsigned long long v, float& x, float& y) {
    asm("mov.b64 {%0, %1}, %2;" : "=f"(x), "=f"(y) : "l"(v));
}
#define FMA2(d, a, b, c) \
    asm("fma.rn.f32x2 %0, %1, %2, %3;" : "=l"(d) : "l"(a), "l"(b), "l"(c))
#define MUL2(d, a, b) \
    asm("mul.rn.f32x2 %0, %1, %2;" : "=l"(d) : "l"(a), "l"(b))

__device__ __forceinline__ float warp_sum(float v) {
#pragma unroll
    for (int o = 16; o > 0; o >>= 1)
        v += __shfl_xor_sync(0xffffffffu, v, o);
    return v;
}

// ---------------- input projection + RoPE ----------------------------------
__global__ void input_rope_kernel(const float* __restrict__ states,
                                  const float* __restrict__ W,
                                  const float* __restrict__ bias,
                                  float* __restrict__ out) {
    int tok = blockIdx.x;
    int l = tok % L_;
    __shared__ float s[STATE_DIM];
    int t = threadIdx.x;  // 256 threads = 256 rope pairs
    if (t < STATE_DIM) s[t] = states[tok * STATE_DIM + t];
    __syncthreads();
    float x1 = bias[2 * t], x2 = bias[2 * t + 1];
#pragma unroll
    for (int k = 0; k < STATE_DIM; k++) {
        float sv = s[k];
        x1 += sv * W[k * D_MODEL + 2 * t];
        x2 += sv * W[k * D_MODEL + 2 * t + 1];
    }
    float inv = expf(-((2.0f * t) / (float)D_MODEL) * logf(10000.0f));
    float fr = (float)l * inv;
    float c = cosf(fr), sn = sinf(fr);
    out[tok * D_MODEL + 2 * t]     = x1 * c - x2 * sn;
    out[tok * D_MODEL + 2 * t + 1] = x1 * sn + x2 * c;
}

// ---------------- layernorm -> split bf16 (warp per token, no barriers) -----
__global__ __launch_bounds__(256) void layernorm_split_kernel(
    const float* __restrict__ x, const float* __restrict__ g,
    const float* __restrict__ b,
    __nv_bfloat16* __restrict__ oh, __nv_bfloat16* __restrict__ ol) {
    int w = threadIdx.x >> 5, lane = threadIdx.x & 31;
    int tok = blockIdx.x * 8 + w;
    const float4* xr = (const float4*)(x + (size_t)tok * D_MODEL);
    float4 a[4];
    float sm = 0.0f, sq = 0.0f;
#pragma unroll
    for (int i = 0; i < 4; i++) {
        a[i] = xr[lane + 32 * i];
        sm += a[i].x + a[i].y + a[i].z + a[i].w;
        sq += a[i].x * a[i].x + a[i].y * a[i].y +
              a[i].z * a[i].z + a[i].w * a[i].w;
    }
    sm = warp_sum(sm);
    sq = warp_sum(sq);
    float mu = sm * (1.0f / D_MODEL);
    float inv = rsqrtf(sq * (1.0f / D_MODEL) - mu * mu + 1e-5f);
    const float4* g4 = (const float4*)g;
    const float4* b4 = (const float4*)b;
    uint2* oh2 = (uint2*)(oh + (size_t)tok * D_MODEL);
    uint2* ol2 = (uint2*)(ol + (size_t)tok * D_MODEL);
#pragma unroll
    for (int i = 0; i < 4; i++) {
        int idx = lane + 32 * i;
        float4 gv = g4[idx], bv = b4[idx];
        float o0 = (a[i].x - mu) * inv * gv.x + bv.x;
        float o1 = (a[i].y - mu) * inv * gv.y + bv.y;
        float o2 = (a[i].z - mu) * inv * gv.z + bv.z;
        float o3 = (a[i].w - mu) * inv * gv.w + bv.w;
        __nv_bfloat16 h0 = __float2bfloat16(o0), h1 = __float2bfloat16(o1);
        __nv_bfloat16 h2 = __float2bfloat16(o2), h3 = __float2bfloat16(o3);
        uint2 hp, lp;
        hp.x = ((uint32_t)__bfloat16_as_ushort(h1) << 16) | __bfloat16_as_ushort(h0);
        hp.y = ((uint32_t)__bfloat16_as_ushort(h3) << 16) | __bfloat16_as_ushort(h2);
        __nv_bfloat16 l0 = __float2bfloat16(o0 - __bfloat162float(h0));
        __nv_bfloat16 l1 = __float2bfloat16(o1 - __bfloat162float(h1));
        __nv_bfloat16 l2 = __float2bfloat16(o2 - __bfloat162float(h2));
        __nv_bfloat16 l3 = __float2bfloat16(o3 - __bfloat162float(h3));
        lp.x = ((uint32_t)__bfloat16_as_ushort(l1) << 16) | __bfloat16_as_ushort(l0);
        lp.y = ((uint32_t)__bfloat16_as_ushort(l3) << 16) | __bfloat16_as_ushort(l2);
        oh2[idx] = hp;
        ol2[idx] = lp;
    }
}

// ---------------- weight transpose + bf16 hi/lo split -----------------------
__global__ void transpose_split_kernel(const float* __restrict__ W,
                                       __nv_bfloat16* __restrict__ Th,
                                       __nv_bfloat16* __restrict__ Tl,
                                       int K, int N) {
    __shared__ float tile[32][33];
    int k0 = blockIdx.x * 32, n0 = blockIdx.y * 32;
    int tx = threadIdx.x, ty = threadIdx.y;  // 32 x 8
#pragma unroll
    for (int r = ty; r < 32; r += 8) {
        int n = n0 + tx;
        tile[r][tx] = (n < N) ? W[(size_t)(k0 + r) * N + n] : 0.0f;
    }
    __syncthreads();
#pragma unroll
    for (int r = ty; r < 32; r += 8) {
        int n = n0 + r, k = k0 + tx;
        if (n < N) {
            float v = tile[tx][r];
            __nv_bfloat16 h = __float2bfloat16(v);
            __nv_bfloat16 l = __float2bfloat16(v - __bfloat162float(h));
            Th[(size_t)n * K + k] = h;
            Tl[(size_t)n * K + k] = l;
        }
    }
}

// ---------------- split-bf16 HMMA GEMM (term-major mma ordering) -------------
#define GKC 32
#define ROWB 80
#define OFF_AH 0
#define OFF_AL 10240
#define OFF_BH 20480
#define OFF_BL 30720
#define STG_BYTES 40960
#define GEMM_SMEM (2 * STG_BYTES)

__device__ __forceinline__ void gemm_fill(
    uint32_t sa, int tid,
    const __nv_bfloat16* __restrict__ Ah, const __nv_bfloat16* __restrict__ Al,
    const __nv_bfloat16* __restrict__ Bh, const __nv_bfloat16* __restrict__ Bl,
    int m0, int n0, int N, int K, int k0) {
#pragma unroll
    for (int c = tid; c < 512; c += 256) {
        int row = c >> 2, q = c & 3;
        uint32_t d = sa + row * ROWB + q * 16;
        size_t aoff = (size_t)(m0 + row) * K + k0 + q * 8;
        CP_ASYNC16(d + OFF_AH, Ah + aoff);
        CP_ASYNC16(d + OFF_AL, Al + aoff);
        int nr = n0 + row; if (nr >= N) nr = N - 1;
        size_t boff = (size_t)nr * K + k0 + q * 8;
        CP_ASYNC16(d + OFF_BH, Bh + boff);
        CP_ASYNC16(d + OFF_BL, Bl + boff);
    }
    CP_COMMIT();
}

__global__ __launch_bounds__(256) void hmma_gemm_kernel(
    const __nv_bfloat16* __restrict__ Ah, const __nv_bfloat16* __restrict__ Al,
    const __nv_bfloat16* __restrict__ Bh, const __nv_bfloat16* __restrict__ Bl,
    const float* __restrict__ bias, const float* __restrict__ res,
    float* __restrict__ C, int M, int N, int K) {
    extern __shared__ char smem[];
    uint32_t sb = smem_to_u32(smem);
    int tid = threadIdx.x;
    int warp = tid >> 5, lane = tid & 31;
    int grp = lane >> 2, qid = lane & 3;
    int wm = (warp >> 2) * 64;
    int wn = (warp & 3) * 32;
    int brow = blockIdx.y, bcol = blockIdx.x;
    int m0 = brow * 128, n0 = bcol * 128;

    float acc[4][4][4];
#pragma unroll
    for (int i = 0; i < 4; i++)
#pragma unroll
        for (int j = 0; j < 4; j++)
#pragma unroll
            for (int r = 0; r < 4; r++) acc[i][j][r] = 0.0f;

    int lr = lane & 7;
    int arow = ((lane >> 3) & 1) * 8;
    int acol = (lane >> 4) * 16;
    int brw  = (lane >> 4) * 8;
    int bcl  = ((lane >> 3) & 1) * 16;

    int nch = K / GKC;
    gemm_fill(sb, tid, Ah, Al, Bh, Bl, m0, n0, N, K, 0);

    for (int ch = 0; ch < nch; ch++) {
        if (ch + 1 < nch) {
            gemm_fill(sb + ((ch + 1) & 1) * STG_BYTES, tid,
                      Ah, Al, Bh, Bl, m0, n0, N, K, (ch + 1) * GKC);
            CP_WAIT1();
        } else {
            CP_WAIT0();
        }
        __syncthreads();
        uint32_t sa = sb + (ch & 1) * STG_BYTES;
#pragma unroll
        for (int ks = 0; ks < 2; ks++) {
            int kb = ks * 32;
            uint32_t ah[4][4], al[4][4];
#pragma unroll
            for (int mi = 0; mi < 4; mi++) {
                uint32_t r = sa + OFF_AH +
                    (uint32_t)((wm + mi * 16 + lr + arow) * ROWB + kb + acol);
                LDMX4(ah[mi], r);
                LDMX4(al[mi], r + (OFF_AL - OFF_AH));
            }
            uint32_t bh[4][2], bl[4][2];
#pragma unroll
            for (int nb = 0; nb < 2; nb++) {
                uint32_t r = sa + OFF_BH +
                    (uint32_t)((wn + nb * 16 + lr + brw) * ROWB + kb + bcl);
                uint32_t tb[4];
                LDMX4(tb, r);
                bh[2 * nb][0] = tb[0]; bh[2 * nb][1] = tb[1];
                bh[2 * nb + 1][0] = tb[2]; bh[2 * nb + 1][1] = tb[3];
                LDMX4(tb, r + (OFF_BL - OFF_BH));
                bl[2 * nb][0] = tb[0]; bl[2 * nb][1] = tb[1];
                bl[2 * nb + 1][0] = tb[2]; bl[2 * nb + 1][1] = tb[3];
            }
            // term-major: same-accumulator reuse spaced 16 mma apart.
            // Per-accumulator contribution order (hh, hl, lh) is unchanged
            // -> bitwise-identical results vs term-minor ordering.
#pragma unroll
            for (int mi = 0; mi < 4; mi++)
#pragma unroll
                for (int ni = 0; ni < 4; ni++)
                    MMA_BF16(acc[mi][ni], ah[mi], bh[ni]);
#pragma unroll
            for (int mi = 0; mi < 4; mi++)
#pragma unroll
                for (int ni = 0; ni < 4; ni++)
                    MMA_BF16(acc[mi][ni], ah[mi], bl[ni]);
#pragma unroll
            for (int mi = 0; mi < 4; mi++)
#pragma unroll
                for (int ni = 0; ni < 4; ni++)
                    MMA_BF16(acc[mi][ni], al[mi], bh[ni]);
        }
        __syncthreads();
    }

#pragma unroll
    for (int mi = 0; mi < 4; mi++) {
#pragma unroll
        for (int half = 0; half < 2; half++) {
            int grow = m0 + wm + mi * 16 + grp + half * 8;
#pragma unroll
            for (int ni = 0; ni < 4; ni++) {
                int gcol = n0 + wn + ni * 8 + qid * 2;
                if (gcol < N) {
                    float v0 = acc[mi][ni][half * 2 + 0];
                    float v1 = acc[mi][ni][half * 2 + 1];
                    if (bias) { v0 += bias[gcol]; v1 += bias[gcol + 1]; }
                    if (res) {
                        const float* rp = res + (size_t)grow * N + gcol;
                        v0 += rp[0]; v1 += rp[1];
                    }
                    *(float2*)(C + (size_t)grow * N + gcol) = make_float2(v0, v1);
                }
            }
        }
    }
}

// ---------------- causal conv1d + SiLU + fused dt/decay ---------------------
#define CTOK 16
__global__ __launch_bounds__(256) void conv_silu_dt_kernel(
    const float* __restrict__ zx, const float* __restrict__ cw,
    const float* __restrict__ cb, const float* __restrict__ dt_bias,
    const float* __restrict__ A_log, float* __restrict__ xbc,
    float* __restrict__ dtd) {
    int c = blockIdx.x * 256 + threadIdx.x;            // 0..1279 (grid.x = 5)
    int by = blockIdx.y;                               // 0..1023
    int b = by >> 6;
    int t0 = (by & 63) * CTOK;
    float4 w = *(const float4*)(cw + c * 4);
    float bias = cb[c];
    const float* p = zx + (size_t)(b * L_ + t0) * D_IN_PROJ + D_INNER + c;
    float* o = xbc + (size_t)(b * L_ + t0) * CONV_DIM + c;
    float x1, x2, x3;   // x_{l-1}, x_{l-2}, x_{l-3}
    if (t0 == 0) {
        x1 = x2 = x3 = 0.0f;
    } else {
        x1 = p[-(int)D_IN_PROJ];
        x2 = p[-2 * (int)D_IN_PROJ];
        x3 = p[-3 * (int)D_IN_PROJ];
    }
#pragma unroll
    for (int i = 0; i < CTOK; i++) {
        float x0 = p[0];
        float acc = bias + w.x * x3 + w.y * x2 + w.z * x1 + w.w * x0;
        o[0] = acc / (1.0f + __expf(-acc));
        x3 = x2; x2 = x1; x1 = x0;
        p += D_IN_PROJ;
        o += CONV_DIM;
    }
    // fused dt/decay: block x=0 handles its 16 tokens x 16 heads
    if (blockIdx.x == 0) {
        int h = threadIdx.x & 15;
        int tok = b * L_ + t0 + (threadIdx.x >> 4);
        float v = zx[(size_t)tok * D_IN_PROJ + D_INNER + CONV_DIM + h]
                  + dt_bias[h];
        float sp = (v > 20.0f) ? v : log1pf(expf(v));
        float A = -expf(A_log[h]);
        size_t i = (size_t)tok * NHEADS + h;
        dtd[2 * i]     = sp;
        dtd[2 * i + 1] = expf(sp * A);
    }
}

// ---------------- selective scan (paired timesteps, cp.async pipelined) -----
// grid = (NHEADS, B_), block 256. Thread t: p = t>>2, q = t&3; owns contiguous
// n in [q*32, q*32+32) as 16 packed f32x2. TWO timesteps per commit group /
// wait / barrier -> fixed overheads amortized over 2 steps.
#define SST 6
__global__ __launch_bounds__(256) void scan_kernel(
    const float* __restrict__ xbc, const float* __restrict__ dtd,
    const float* __restrict__ Dp, float* __restrict__ y) {
    int h = blockIdx.x, b = blockIdx.y;
    int t = threadIdx.x;
    int p = t >> 2;
    int q = t & 3;
    __shared__ float4 sB4[SST][36], sC4[SST][36];   // 4 q-rows x 9 float4 (pad)
    __shared__ float sX[SST][HEADDIM];
    __shared__ float2 sDt[SST];
    float Dh = Dp[h];
    unsigned long long s2[16];
#pragma unroll
    for (int j = 0; j < 16; j++) s2[j] = 0ull;

    uint32_t aB = smem_to_u32(sB4);
    uint32_t aC = smem_to_u32(sC4);
    uint32_t aX = smem_to_u32(sX);
    uint32_t aD = smem_to_u32(sDt);

    const float* xb0 = xbc + (size_t)(b * L_) * CONV_DIM;
    const float* dt0 = dtd + (size_t)(b * L_) * (NHEADS * 2) + h * 2;

#define SCAN_ISSUE(l) do {                                                    \
        int _st = (l) % SST;                                                  \
        const float* _base = xb0 + (size_t)(l) * CONV_DIM;                    \
        if (t < 32) {                                                         \
            CP_ASYNC16(aB + _st * 576 + (t >> 3) * 144 + (t & 7) * 16,        \
                       _base + D_INNER + t * 4);                              \
        } else if (t < 64) {                                                  \
            int _i = t - 32;                                                  \
            CP_ASYNC16(aC + _st * 576 + (_i >> 3) * 144 + (_i & 7) * 16,      \
                       _base + D_INNER + D_STATE + _i * 4);                   \
        } else if (t < 80) {                                                  \
            int _i = t - 64;                                                  \
            CP_ASYNC16(aX + _st * 256 + _i * 16, _base + h * HEADDIM + _i * 4); \
        } else if (t == 80) {                                                 \
            CP_ASYNC8(aD + _st * 8, dt0 + (size_t)(l) * (NHEADS * 2));        \
        }                                                                     \
    } while (0)

    // one step per thread-role step, two timesteps per commit group
#define SCAN_STEP(cur) do {                                                   \
        float2 dd = sDt[cur];                                                 \
        float dtv = dd.x, dec = dd.y;                                         \
        float xp = sX[cur][p];                                                \
        float dtx = dtv * xp;                                                 \
        unsigned long long dec2 = pk2(dec, dec);                              \
        unsigned long long dtx2 = pk2(dtx, dtx);                              \
        unsigned long long acc2 = 0ull;                                       \
        _Pragma("unroll")                                                     \
        for (int jj = 0; jj < 8; jj++) {                                      \
            ulonglong2 b2 = *(const ulonglong2*)&sB4[cur][q9 + jj];           \
            ulonglong2 c2 = *(const ulonglong2*)&sC4[cur][q9 + jj];           \
            unsigned long long tmp;                                           \
            MUL2(tmp, dtx2, b2.x);                                            \
            FMA2(s2[2 * jj], s2[2 * jj], dec2, tmp);                          \
            FMA2(acc2, s2[2 * jj], c2.x, acc2);                               \
            MUL2(tmp, dtx2, b2.y);                                            \
            FMA2(s2[2 * jj + 1], s2[2 * jj + 1], dec2, tmp);                  \
            FMA2(acc2, s2[2 * jj + 1], c2.y, acc2);                           \
        }                                                                     \
        float a0, a1;                                                         \
        upk2(acc2, a0, a1);                                                   \
        float acc = a0 + a1;                                                  \
        acc += __shfl_xor_sync(0xffffffffu, acc, 1);                          \
        acc += __shfl_xor_sync(0xffffffffu, acc, 2);                          \
        if (q == 0)                                                           \
            y[(size_t)(b * L_ + lcur) * D_INNER + h * HEADDIM + p] =          \
                acc + Dh * xp;                                                \
    } while (0)

    SCAN_ISSUE(0); SCAN_ISSUE(1); CP_COMMIT();
    SCAN_ISSUE(2); SCAN_ISSUE(3); CP_COMMIT();

    int q9 = q * 9;
    for (int l = 0; l < L_; l += 2) {
        CP_WAIT1();
        __syncthreads();
        {
            int lcur = l;
            int cur = l % SST;
            SCAN_STEP(cur);
        }
        {
            int lcur = l + 1;
            int cur = (l + 1) % SST;
            SCAN_STEP(cur);
        }
        if (l + 4 < L_) { SCAN_ISSUE(l + 4); SCAN_ISSUE(l + 5); }
        CP_COMMIT();   // always commit: keeps group-count invariant
    }
#undef SCAN_STEP
#undef SCAN_ISSUE
}

// ---------------- gate (y * silu(z)) + RMSNorm -> split bf16 (warp/token) ---
__global__ __launch_bounds__(256) void gate_rms_split_kernel(
    const float* __restrict__ zx, const float* __restrict__ rms_w,
    const float* __restrict__ y,
    __nv_bfloat16* __restrict__ oh, __nv_bfloat16* __restrict__ ol) {
    int w = threadIdx.x >> 5, lane = threadIdx.x & 31;
    int tok = blockIdx.x * 8 + w;
    const float4* zr = (const float4*)(zx + (size_t)tok * D_IN_PROJ);
    const float4* yr = (const float4*)(y + (size_t)tok * D_INNER);
    float v[32];
    float ss = 0.0f;
#pragma unroll
    for (int i = 0; i < 8; i++) {
        int idx = lane + 32 * i;
        float4 z4 = zr[idx];
        float4 y4 = yr[idx];
        float g0 = z4.x / (1.0f + __expf(-z4.x));
        float g1 = z4.y / (1.0f + __expf(-z4.y));
        float g2 = z4.z / (1.0f + __expf(-z4.z));
        float g3 = z4.w / (1.0f + __expf(-z4.w));
        v[4 * i + 0] = y4.x * g0;
        v[4 * i + 1] = y4.y * g1;
        v[4 * i + 2] = y4.z * g2;
        v[4 * i + 3] = y4.w * g3;
        ss += v[4 * i] * v[4 * i] + v[4 * i + 1] * v[4 * i + 1] +
              v[4 * i + 2] * v[4 * i + 2] + v[4 * i + 3] * v[4 * i + 3];
    }
    ss = warp_sum(ss);
    float inv = rsqrtf(ss * (1.0f / D_INNER) + 1e-5f);
    const float4* r4 = (const float4*)rms_w;
    uint2* oh2 = (uint2*)(oh + (size_t)tok * D_INNER);
    uint2* ol2 = (uint2*)(ol + (size_t)tok * D_INNER);
#pragma unroll
    for (int i = 0; i < 8; i++) {
        int idx = lane + 32 * i;
        float4 rw = r4[idx];
        float o0 = v[4 * i + 0] * inv * rw.x;
        float o1 = v[4 * i + 1] * inv * rw.y;
        float o2 = v[4 * i + 2] * inv * rw.z;
        float o3 = v[4 * i + 3] * inv * rw.w;
        __nv_bfloat16 h0 = __float2bfloat16(o0), h1 = __float2bfloat16(o1);
        __nv_bfloat16 h2 = __float2bfloat16(o2), h3 = __float2bfloat16(o3);
        uint2 hp, lp;
        hp.x = ((uint32_t)__bfloat16_as_ushort(h1) << 16) | __bfloat16_as_ushort(h0);
        hp.y = ((uint32_t)__bfloat16_as_ushort(h3) << 16) | __bfloat16_as_ushort(h2);
        __nv_bfloat16 l0 = __float2bfloat16(o0 - __bfloat162float(h0));
        __nv_bfloat16 l1 = __float2bfloat16(o1 - __bfloat162float(h1));
        __nv_bfloat16 l2 = __float2bfloat16(o2 - __bfloat162float(h2));
        __nv_bfloat16 l3 = __float2bfloat16(o3 - __bfloat162float(h3));
        lp.x = ((uint32_t)__bfloat16_as_ushort(l1) << 16) | __bfloat16_as_ushort(l0);
        lp.y = ((uint32_t)__bfloat16_as_ushort(l3) << 16) | __bfloat16_as_ushort(l2);
        oh2[idx] = hp;
        ol2[idx] = lp;
    }
}

// ---------------- launch -----------------------------------------------------
extern "C" void kernel_launch(void* const* d_in, const int* in_sizes, int n_in,
                              void* d_out, int out_size) {
    const float* states        = (const float*)d_in[0];
    const float* input_proj_w  = (const float*)d_in[1];
    const float* input_proj_b  = (const float*)d_in[2];
    const float* ln_g          = (const float*)d_in[3];
    const float* ln_b          = (const float*)d_in[4];
    const float* in_proj_w     = (const float*)d_in[5];
    const float* conv_w        = (const float*)d_in[6];
    const float* conv_b        = (const float*)d_in[7];
    const float* dt_bias       = (const float*)d_in[8];
    const float* A_log         = (const float*)d_in[9];
    const float* D_param       = (const float*)d_in[10];
    const float* rms_w         = (const float*)d_in[11];
    const float* out_proj_w    = (const float*)d_in[12];
    const float* post_ln_g     = (const float*)d_in[13];
    const float* post_ln_b     = (const float*)d_in[14];
    const float* output_proj_w = (const float*)d_in[15];
    const float* output_proj_b = (const float*)d_in[16];

    float *px, *pzx, *pxbc, *pdtd, *py;
    cudaGetSymbolAddress((void**)&px, g_x);
    cudaGetSymbolAddress((void**)&pzx, g_zx);
    cudaGetSymbolAddress((void**)&pxbc, g_xbc);
    cudaGetSymbolAddress((void**)&pdtd, g_dtd);
    cudaGetSymbolAddress((void**)&py, g_y);
    __nv_bfloat16 *phh, *phl, *pyh, *pyl;
    cudaGetSymbolAddress((void**)&phh, g_hh);
    cudaGetSymbolAddress((void**)&phl, g_hl);
    cudaGetSymbolAddress((void**)&pyh, g_yh);
    cudaGetSymbolAddress((void**)&pyl, g_yl);
    __nv_bfloat16 *pwih, *pwil, *pwoh, *pwol, *pwfh, *pwfl;
    cudaGetSymbolAddress((void**)&pwih, g_wih);
    cudaGetSymbolAddress((void**)&pwil, g_wil);
    cudaGetSymbolAddress((void**)&pwoh, g_woh);
    cudaGetSymbolAddress((void**)&pwol, g_wol);
    cudaGetSymbolAddress((void**)&pwfh, g_wfh);
    cudaGetSymbolAddress((void**)&pwfl, g_wfl);

    cudaFuncSetAttribute(hmma_gemm_kernel,
                         cudaFuncAttributeMaxDynamicSharedMemorySize, GEMM_SMEM);

    dim3 tb(32, 8);
    // ---- layer-0 weights first so ncu capture slot (-s 5) = in_proj GEMM ----
    transpose_split_kernel<<<dim3(D_MODEL / 32, (D_IN_PROJ + 31) / 32), tb>>>(  // 0
        in_proj_w, pwih, pwil, D_MODEL, D_IN_PROJ);
    transpose_split_kernel<<<dim3(D_INNER / 32, D_MODEL / 32), tb>>>(           // 1
        out_proj_w, pwoh, pwol, D_INNER, D_MODEL);
    transpose_split_kernel<<<dim3(D_MODEL / 32, D_MODEL / 32), tb>>>(           // 2
        output_proj_w, pwfh, pwfl, D_MODEL, D_MODEL);
    input_rope_kernel<<<NTOK, 256>>>(states, input_proj_w, input_proj_b, px);   // 3
    layernorm_split_kernel<<<NTOK / 8, 256>>>(px, ln_g, ln_b, phh, phl);        // 4

    dim3 g1((D_IN_PROJ + 127) / 128, NTOK / 128);
    dim3 g2(D_MODEL / 128, NTOK / 128);

    hmma_gemm_kernel<<<g1, 256, GEMM_SMEM>>>(                                   // 5 <- ncu
        phh, phl, pwih, pwil, nullptr, nullptr, pzx, NTOK, D_IN_PROJ, D_MODEL);

    // remaining layers' weight prep (independent; scheduled after capture slot)
    for (int l = 1; l < N_LAYERS; l++) {
        transpose_split_kernel<<<dim3(D_MODEL / 32, (D_IN_PROJ + 31) / 32), tb>>>(
            in_proj_w + (size_t)l * D_MODEL * D_IN_PROJ,
            pwih + (size_t)l * D_IN_PROJ * D_MODEL,
            pwil + (size_t)l * D_IN_PROJ * D_MODEL, D_MODEL, D_IN_PROJ);
        transpose_split_kernel<<<dim3(D_INNER / 32, D_MODEL / 32), tb>>>(
            out_proj_w + (size_t)l * D_INNER * D_MODEL,
            pwoh + (size_t)l * D_MODEL * D_INNER,
            pwol + (size_t)l * D_MODEL * D_INNER, D_INNER, D_MODEL);
    }

    for (int l = 0; l < N_LAYERS; l++) {
        if (l > 0) {
            layernorm_split_kernel<<<NTOK / 8, 256>>>(px, ln_g + l * D_MODEL,
                                                      ln_b + l * D_MODEL, phh, phl);
            hmma_gemm_kernel<<<g1, 256, GEMM_SMEM>>>(
                phh, phl,
                pwih + (size_t)l * D_IN_PROJ * D_MODEL,
                pwil + (size_t)l * D_IN_PROJ * D_MODEL,
                nullptr, nullptr, pzx, NTOK, D_IN_PROJ, D_MODEL);
        }

        conv_silu_dt_kernel<<<dim3(5, B_ * (L_ / CTOK)), 256>>>(
            pzx, conv_w + (size_t)l * CONV_DIM * D_CONV,
            conv_b + (size_t)l * CONV_DIM, dt_bias + l * NHEADS,
            A_log + l * NHEADS, pxbc, pdtd);

        scan_kernel<<<dim3(NHEADS, B_), 256>>>(pxbc, pdtd,
                                               D_param + l * NHEADS, py);

        gate_rms_split_kernel<<<NTOK / 8, 256>>>(pzx, rms_w + (size_t)l * D_INNER,
                                                 py, pyh, pyl);

        hmma_gemm_kernel<<<g2, 256, GEMM_SMEM>>>(
            pyh, pyl,
            pwoh + (size_t)l * D_MODEL * D_INNER,
            pwol + (size_t)l * D_MODEL * D_INNER,
            nullptr, px, px, NTOK, D_MODEL, D_INNER);
    }

    layernorm_split_kernel<<<NTOK / 8, 256>>>(px, post_ln_g, post_ln_b, phh, phl);
    dim3 g3(D_MODEL / 128, NTOK / 128);
    hmma_gemm_kernel<<<g3, 256, GEMM_SMEM>>>(
        phh, phl, pwfh, pwfl, output_proj_b, nullptr,
        (float*)d_out, NTOK, D_MODEL, D_MODEL);
}